// round 4
// baseline (speedup 1.0000x reference)
#include <cuda_runtime.h>
#include <cstddef>

#define VOCABN 50000
#define DIMN   300
#define HN     100
#define TN     512
#define BN     256
#define OUTN   3
#define G4     400   // 4*H
#define KP0    304   // padded K for layer-0 table GEMM (emb K=300)
#define KP1    112   // padded K for xg GEMMs (h K=100)

// ---------------- scratch (static device globals; no allocation) ----------------
__device__ float g_table[(size_t)VOCABN * G4];
__device__ float g_xg[(size_t)BN * TN * G4];
__device__ float g_h[(size_t)BN * TN * HN];
__device__ float g_hlast[BN * HN];
__device__ int   g_order[BN];
__device__ float g_w0p[G4 * KP0];   // w_ih0 zero-padded to K=304
__device__ float g_w1p[G4 * KP1];   // w_ih1 zero-padded to K=112
__device__ float g_w2p[G4 * KP1];   // w_ih2 zero-padded to K=112

// ---------------- packed f32x2 helpers (Blackwell) ----------------
typedef unsigned long long ull;

__device__ __forceinline__ ull pack2(float x, float y) {
    ull r;
    asm("mov.b64 %0, {%1, %2};" : "=l"(r) : "f"(x), "f"(y));
    return r;
}
__device__ __forceinline__ void unpack2(ull v, float& x, float& y) {
    asm("mov.b64 {%0, %1}, %2;" : "=f"(x), "=f"(y) : "l"(v));
}
__device__ __forceinline__ ull fma2(ull a, ull b, ull c) {
    ull d;
    asm("fma.rn.f32x2 %0, %1, %2, %3;" : "=l"(d) : "l"(a), "l"(b), "l"(c));
    return d;
}

// ---------------- length-descending schedule ----------------
__global__ void sort_order(const int* __restrict__ lengths, int* __restrict__ order)
{
    __shared__ int ls[BN];
    int b = threadIdx.x;
    ls[b] = lengths[b];
    __syncthreads();
    int len = ls[b];
    int rank = 0;
#pragma unroll 8
    for (int j = 0; j < BN; j++) {
        int lj = ls[j];
        rank += (lj > len) || (lj == len && j < b);
    }
    order[rank] = b;
}

// ---------------- weight zero-padding ----------------
__global__ void pad_w(const float* __restrict__ src, float* __restrict__ dst,
                      int K, int Kp)
{
    int idx = blockIdx.x * 256 + threadIdx.x;
    int total = G4 * Kp;
    if (idx >= total) return;
    int r = idx / Kp, k = idx % Kp;
    dst[idx] = (k < K) ? src[r * K + k] : 0.f;
}

// ---------------- GEMM: C[m,n] = sum_k A[m,k]*Bp[n,k] + bias1[n] + bias2[n] -----
// 128x64 tile, BK=16, 128 threads, 8x8 microtile, f32x2 FMA,
// register double-buffered global loads, clamp-style bounds (B is zero-padded).
template<int SKIP>
__global__ void __launch_bounds__(128)
gemm_tn(const float* __restrict__ A, int M, int Ks, int Kreal,
        const float* __restrict__ Bp, int N, int Kp,
        const float* __restrict__ bias1, const float* __restrict__ bias2,
        const int* __restrict__ lengths,
        float* __restrict__ C)
{
    __shared__ __align__(16) float As[16][132];
    __shared__ __align__(16) float Bs[16][68];

    const int m0 = blockIdx.y * 128;
    const int n0 = blockIdx.x * 64;
    if (SKIP) {
        int b  = m0 / TN;
        int t0 = m0 % TN;
        if (t0 >= lengths[b]) return;
    }
    const int tid = threadIdx.x;
    const int tx = tid & 7;
    const int ty = tid >> 3;
    const int kclA = Kreal - 4;             // clamp: OOB k multiplies zero-padded B

    // per-thread load coords (constant across iterations)
    int rowA[4], kqA[4], rowB[2], kqB[2];
#pragma unroll
    for (int i = 0; i < 4; i++) { int f = i * 128 + tid; rowA[i] = f >> 2; kqA[i] = (f & 3) * 4; }
#pragma unroll
    for (int i = 0; i < 2; i++) { int f = i * 128 + tid; rowB[i] = f >> 2; kqB[i] = (f & 3) * 4; }

    const float* aptr[4];
    const float* bptr[2];
#pragma unroll
    for (int i = 0; i < 4; i++) {
        int m = m0 + rowA[i]; if (m > M - 1) m = M - 1;
        aptr[i] = A + (size_t)m * Ks;
    }
#pragma unroll
    for (int i = 0; i < 2; i++) {
        int n = n0 + rowB[i]; if (n > N - 1) n = N - 1;
        bptr[i] = Bp + (size_t)n * Kp;
    }

    ull acc[8][4];
#pragma unroll
    for (int i = 0; i < 8; i++)
#pragma unroll
        for (int j = 0; j < 4; j++) acc[i][j] = 0ULL;

    float4 ra[4], rb[2];
    // prefetch first tile
#pragma unroll
    for (int i = 0; i < 4; i++) {
        int k = kqA[i]; if (k > kclA) k = kclA;
        ra[i] = *reinterpret_cast<const float4*>(aptr[i] + k);
    }
#pragma unroll
    for (int i = 0; i < 2; i++)
        rb[i] = *reinterpret_cast<const float4*>(bptr[i] + kqB[i]);

    for (int k0 = 0; k0 < Kp; k0 += 16) {
        // stage registers -> smem (transposed)
#pragma unroll
        for (int i = 0; i < 4; i++) {
            As[kqA[i] + 0][rowA[i]] = ra[i].x; As[kqA[i] + 1][rowA[i]] = ra[i].y;
            As[kqA[i] + 2][rowA[i]] = ra[i].z; As[kqA[i] + 3][rowA[i]] = ra[i].w;
        }
#pragma unroll
        for (int i = 0; i < 2; i++) {
            Bs[kqB[i] + 0][rowB[i]] = rb[i].x; Bs[kqB[i] + 1][rowB[i]] = rb[i].y;
            Bs[kqB[i] + 2][rowB[i]] = rb[i].z; Bs[kqB[i] + 3][rowB[i]] = rb[i].w;
        }
        __syncthreads();

        // prefetch next tile (overlaps with compute below)
        int k0n = k0 + 16;
        if (k0n < Kp) {
#pragma unroll
            for (int i = 0; i < 4; i++) {
                int k = k0n + kqA[i]; if (k > kclA) k = kclA;
                ra[i] = *reinterpret_cast<const float4*>(aptr[i] + k);
            }
#pragma unroll
            for (int i = 0; i < 2; i++)
                rb[i] = *reinterpret_cast<const float4*>(bptr[i] + k0n + kqB[i]);
        }

#pragma unroll
        for (int k = 0; k < 16; k++) {
            float4 a0 = *reinterpret_cast<const float4*>(&As[k][ty * 8]);
            float4 a1 = *reinterpret_cast<const float4*>(&As[k][ty * 8 + 4]);
            ulonglong2 b0 = *reinterpret_cast<const ulonglong2*>(&Bs[k][tx * 8]);
            ulonglong2 b1 = *reinterpret_cast<const ulonglong2*>(&Bs[k][tx * 8 + 4]);
            float am[8] = {a0.x, a0.y, a0.z, a0.w, a1.x, a1.y, a1.z, a1.w};
#pragma unroll
            for (int i = 0; i < 8; i++) {
                ull ai = pack2(am[i], am[i]);
                acc[i][0] = fma2(ai, b0.x, acc[i][0]);
                acc[i][1] = fma2(ai, b0.y, acc[i][1]);
                acc[i][2] = fma2(ai, b1.x, acc[i][2]);
                acc[i][3] = fma2(ai, b1.y, acc[i][3]);
            }
        }
        __syncthreads();
    }
#pragma unroll
    for (int i = 0; i < 8; i++) {
        int m = m0 + ty * 8 + i;
        if (m >= M) continue;
        float cv[8];
        unpack2(acc[i][0], cv[0], cv[1]);
        unpack2(acc[i][1], cv[2], cv[3]);
        unpack2(acc[i][2], cv[4], cv[5]);
        unpack2(acc[i][3], cv[6], cv[7]);
#pragma unroll
        for (int j = 0; j < 8; j++) {
            int n = n0 + tx * 8 + j;
            if (n < N)
                C[(size_t)m * N + n] = cv[j] + bias1[n] + bias2[n];
        }
    }
}

// ---------------- LSTM scan (chunk-split matvec, 2 batch elements / CTA) -------
__device__ __forceinline__ float tanh_(float x) { return 2.f / (1.f + __expf(-2.f * x)) - 1.f; }

// select s[g^X] from 4 scalar regs without dynamic indexing
__device__ __forceinline__ float sel0(int g, float s0, float s1, float s2, float s3) { // s[g]
    return (g & 1) ? ((g & 2) ? s3 : s1) : ((g & 2) ? s2 : s0);
}
__device__ __forceinline__ float sel1(int g, float s0, float s1, float s2, float s3) { // s[g^1]
    return (g & 1) ? ((g & 2) ? s2 : s0) : ((g & 2) ? s3 : s1);
}
__device__ __forceinline__ float sel2(int g, float s0, float s1, float s2, float s3) { // s[g^2]
    return (g & 1) ? ((g & 2) ? s1 : s3) : ((g & 2) ? s0 : s2);
}
__device__ __forceinline__ float sel3(int g, float s0, float s1, float s2, float s3) { // s[g^3]
    return (g & 1) ? ((g & 2) ? s0 : s2) : ((g & 2) ? s1 : s3);
}

// quad transpose-reduce: lane g of each quad returns sum over all 4 chunks of gate g
__device__ __forceinline__ float quad_reduce(unsigned mask, int g,
                                             float s0, float s1, float s2, float s3)
{
    float r1 = __shfl_xor_sync(mask, sel1(g, s0, s1, s2, s3), 1);
    float u1 = sel0(g, s0, s1, s2, s3) + r1;          // gate g over chunks {g, g^1}
    float r2 = __shfl_xor_sync(mask, sel3(g, s0, s1, s2, s3), 1);
    float u2 = sel2(g, s0, s1, s2, s3) + r2;          // gate g^2 over chunks {g, g^1}
    float r3 = __shfl_xor_sync(mask, u2, 2);          // gate g over chunks {g^2, g^3}
    return u1 + r3;
}

// thread tid = j*4 + g : hidden unit j (0..99), lane-role g (chunk & gate id)
// Each CTA processes TWO batch elements: order[blockIdx.x] and order[255-blockIdx.x].
// MODE 0: layer 0 (gather from table via tokens), writes h_out
// MODE 1: middle layer (xg buffer),               writes h_out
// MODE 2: last layer (xg buffer),                 writes hlast only
template<int MODE>
__global__ void __launch_bounds__(400, 1)
lstm_scan(const float* __restrict__ xg,
          const int* __restrict__ xtok,
          const int* __restrict__ lengths,
          const int* __restrict__ order,
          const float* __restrict__ w_hh,     // [400,100]
          float* __restrict__ h_out,          // [B,T,100]
          float* __restrict__ hlast)          // [B,100]
{
    const int e0 = order[blockIdx.x];
    const int e1 = order[BN - 1 - blockIdx.x];
    const int tid = threadIdx.x;
    const int j   = tid >> 2;
    const int g   = tid & 3;
    const int r   = g * 100 + j;               // this lane's gate row (for xg)
    const unsigned mask = (tid >= 384) ? 0xFFFFu : 0xFFFFFFFFu;

    // h state: [elem][ping][chunk(4) * 28]; chunk c holds h[c*25 .. c*25+24]
    __shared__ __align__(16) float h_s[2][2][4 * 28];
    __shared__ int idx_s[2][TN];

    const int len0 = lengths[e0];
    const int len1 = lengths[e1];
    const int lenmax = (len0 > len1) ? len0 : len1;

    if (MODE == 0) {
        for (int t = tid; t < TN; t += 400) {
            idx_s[0][t] = xtok[e0 * TN + t];
            idx_s[1][t] = xtok[e1 * TN + t];
        }
    }

    // weights: lane (j,g) holds, for all 4 gate rows of unit j, the h-chunk g
    ull   wp[4][12];
    float wl[4];
#pragma unroll
    for (int gp = 0; gp < 4; gp++) {
        const float* wr = w_hh + (size_t)(gp * 100 + j) * 100 + g * 25;
#pragma unroll
        for (int q = 0; q < 12; q++) wp[gp][q] = pack2(wr[2 * q], wr[2 * q + 1]);
        wl[gp] = wr[24];
    }

    const int jc = (j / 25) * 28 + (j % 25);   // smem slot of unit j
    if (g == 0) { h_s[0][0][jc] = 0.f; h_s[1][0][jc] = 0.f; }
    float c0 = 0.f, c1 = 0.f, hk0 = 0.f, hk1 = 0.f;
    __syncthreads();

    const bool is_t = (g == 2);

    // prefetch xg rows for t=0
    float xv0, xv1;
    if (MODE == 0) {
        xv0 = xg[(size_t)idx_s[0][0] * G4 + r];
        xv1 = xg[(size_t)idx_s[1][0] * G4 + r];
    } else {
        xv0 = xg[((size_t)e0 * TN) * G4 + r];
        xv1 = xg[((size_t)e1 * TN) * G4 + r];
    }

    for (int t = 0; t < lenmax; t++) {
        float x0 = xv0, x1 = xv1;
        {
            int tn0 = t + 1 < len0 ? t + 1 : len0 - 1;
            int tn1 = t + 1 < len1 ? t + 1 : len1 - 1;
            if (MODE == 0) {
                xv0 = xg[(size_t)idx_s[0][tn0] * G4 + r];
                xv1 = xg[(size_t)idx_s[1][tn1] * G4 + r];
            } else {
                xv0 = xg[((size_t)e0 * TN + tn0) * G4 + r];
                xv1 = xg[((size_t)e1 * TN + tn1) * G4 + r];
            }
        }

        // chunk matvec for both elements: 4 gate-partials each
        const float* hca = &h_s[0][t & 1][g * 28];
        const float* hcb = &h_s[1][t & 1][g * 28];
        const ull* h2a = reinterpret_cast<const ull*>(hca);
        const ull* h2b = reinterpret_cast<const ull*>(hcb);
        ull a0 = 0, a1 = 0, a2 = 0, a3 = 0;
        ull b0 = 0, b1 = 0, b2 = 0, b3 = 0;
#pragma unroll
        for (int q = 0; q < 12; q++) {
            ull ha = h2a[q], hb = h2b[q];
            a0 = fma2(ha, wp[0][q], a0);
            a1 = fma2(ha, wp[1][q], a1);
            a2 = fma2(ha, wp[2][q], a2);
            a3 = fma2(ha, wp[3][q], a3);
            b0 = fma2(hb, wp[0][q], b0);
            b1 = fma2(hb, wp[1][q], b1);
            b2 = fma2(hb, wp[2][q], b2);
            b3 = fma2(hb, wp[3][q], b3);
        }
        float hla = hca[24], hlb = hcb[24];
        float lo, hi;
        float sA0, sA1, sA2, sA3, sB0, sB1, sB2, sB3;
        unpack2(a0, lo, hi); sA0 = lo + hi + hla * wl[0];
        unpack2(a1, lo, hi); sA1 = lo + hi + hla * wl[1];
        unpack2(a2, lo, hi); sA2 = lo + hi + hla * wl[2];
        unpack2(a3, lo, hi); sA3 = lo + hi + hla * wl[3];
        unpack2(b0, lo, hi); sB0 = lo + hi + hlb * wl[0];
        unpack2(b1, lo, hi); sB1 = lo + hi + hlb * wl[1];
        unpack2(b2, lo, hi); sB2 = lo + hi + hlb * wl[2];
        unpack2(b3, lo, hi); sB3 = lo + hi + hlb * wl[3];

        float accA = quad_reduce(mask, g, sA0, sA1, sA2, sA3) + x0;
        float accB = quad_reduce(mask, g, sB0, sB1, sB2, sB3) + x1;

        // activation (sigmoid for g=0,1,3; tanh for g=2), divergence-free
        float zA = is_t ? 2.f * accA : accA;
        float zB = is_t ? 2.f * accB : accB;
        float eA = 1.f / (1.f + __expf(-zA));
        float eB = 1.f / (1.f + __expf(-zB));
        float gateA = is_t ? (2.f * eA - 1.f) : eA;
        float gateB = is_t ? (2.f * eB - 1.f) : eB;

        // quad exchange: collect i,f,g,o in every lane (both elements)
        const bool gsel = (g & 2) != 0;
        float v1A = __shfl_xor_sync(mask, gateA, 1);
        float v1B = __shfl_xor_sync(mask, gateB, 1);
        float paA = (g & 1) ? v1A : gateA, pbA = (g & 1) ? gateA : v1A;
        float paB = (g & 1) ? v1B : gateB, pbB = (g & 1) ? gateB : v1B;
        float qaA = __shfl_xor_sync(mask, paA, 2);
        float qbA = __shfl_xor_sync(mask, pbA, 2);
        float qaB = __shfl_xor_sync(mask, paB, 2);
        float qbB = __shfl_xor_sync(mask, pbB, 2);
        float igA = gsel ? qaA : paA, ggA = gsel ? paA : qaA;
        float fgA = gsel ? qbA : pbA, ogA = gsel ? pbA : qbA;
        float igB = gsel ? qaB : paB, ggB = gsel ? paB : qaB;
        float fgB = gsel ? qbB : pbB, ogB = gsel ? pbB : qbB;

        // cell updates (state frozen past sequence end)
        bool v0 = (t < len0), v1v = (t < len1);
        float cn0 = fgA * c0 + igA * ggA;
        float cn1 = fgB * c1 + igB * ggB;
        float hn0 = ogA * tanh_(cn0);
        float hn1 = ogB * tanh_(cn1);
        c0 = v0 ? cn0 : c0;
        c1 = v1v ? cn1 : c1;
        if (g == 0) {
            hk0 = v0 ? hn0 : hk0;
            hk1 = v1v ? hn1 : hk1;
            h_s[0][(t + 1) & 1][jc] = hk0;
            h_s[1][(t + 1) & 1][jc] = hk1;
            if (MODE != 2) {
                if (v0)  h_out[((size_t)e0 * TN + t) * HN + j] = hn0;
                if (v1v) h_out[((size_t)e1 * TN + t) * HN + j] = hn1;
            } else {
                if (t == len0 - 1) hlast[e0 * HN + j] = hn0;
                if (t == len1 - 1) hlast[e1 * HN + j] = hn1;
            }
        }
        __syncthreads();
    }
}

// ---------------- head ----------------
__global__ void head_kernel(const float* __restrict__ hlast,
                            const float* __restrict__ w_fc,
                            const float* __restrict__ b_fc,
                            float* __restrict__ out)
{
    int b = blockIdx.x * blockDim.x + threadIdx.x;
    if (b >= BN) return;
#pragma unroll
    for (int o = 0; o < OUTN; o++) {
        float s = b_fc[o];
#pragma unroll
        for (int k = 0; k < HN; k++)
            s += hlast[b * HN + k] * w_fc[o * HN + k];
        out[b * OUTN + o] = s;
    }
}

// ---------------- launch ----------------
extern "C" void kernel_launch(void* const* d_in, const int* in_sizes, int n_in,
                              void* d_out, int out_size)
{
    const int*   x      = (const int*)d_in[0];
    const int*   lens   = (const int*)d_in[1];
    const float* emb    = (const float*)d_in[2];
    const float* w_ih0  = (const float*)d_in[3];
    const float* w_hh0  = (const float*)d_in[4];
    const float* b_ih0  = (const float*)d_in[5];
    const float* b_hh0  = (const float*)d_in[6];
    const float* w_ih1  = (const float*)d_in[7];
    const float* w_hh1  = (const float*)d_in[8];
    const float* b_ih1  = (const float*)d_in[9];
    const float* b_hh1  = (const float*)d_in[10];
    const float* w_ih2  = (const float*)d_in[11];
    const float* w_hh2  = (const float*)d_in[12];
    const float* b_ih2  = (const float*)d_in[13];
    const float* b_hh2  = (const float*)d_in[14];
    const float* w_fc   = (const float*)d_in[15];
    const float* b_fc   = (const float*)d_in[16];
    float* out = (float*)d_out;

    void *p_table, *p_xg, *p_h, *p_hlast, *p_order, *p_w0, *p_w1, *p_w2;
    cudaGetSymbolAddress(&p_table, g_table);
    cudaGetSymbolAddress(&p_xg,    g_xg);
    cudaGetSymbolAddress(&p_h,     g_h);
    cudaGetSymbolAddress(&p_hlast, g_hlast);
    cudaGetSymbolAddress(&p_order, g_order);
    cudaGetSymbolAddress(&p_w0,    g_w0p);
    cudaGetSymbolAddress(&p_w1,    g_w1p);
    cudaGetSymbolAddress(&p_w2,    g_w2p);
    float* table = (float*)p_table;
    float* xg    = (float*)p_xg;
    float* h     = (float*)p_h;
    float* hlast = (float*)p_hlast;
    int*   order = (int*)p_order;
    float* w0p   = (float*)p_w0;
    float* w1p   = (float*)p_w1;
    float* w2p   = (float*)p_w2;

    const int M = BN * TN;
    dim3 blk(128);

    // 0) schedule + weight padding
    sort_order<<<1, BN>>>(lens, order);
    pad_w<<<(G4 * KP0 + 255) / 256, 256>>>(w_ih0, w0p, DIMN, KP0);
    pad_w<<<(G4 * KP1 + 255) / 256, 256>>>(w_ih1, w1p, HN, KP1);
    pad_w<<<(G4 * KP1 + 255) / 256, 256>>>(w_ih2, w2p, HN, KP1);

    // 1) vocab table GEMM: table = emb @ w_ih0^T + b_ih0 + b_hh0
    {
        dim3 grid((G4 + 63) / 64, (VOCABN + 127) / 128);
        gemm_tn<0><<<grid, blk>>>(emb, VOCABN, DIMN, DIMN, w0p, G4, KP0,
                                  b_ih0, b_hh0, nullptr, table);
    }
    // 2) layer 0 scan (gathers table rows directly)
    lstm_scan<0><<<BN / 2, 400>>>(table, x, lens, order, w_hh0, h, nullptr);

    // 3) layer 1 xg GEMM (+length tile-skip), then scan
    {
        dim3 grid((G4 + 63) / 64, M / 128);
        gemm_tn<1><<<grid, blk>>>(h, M, HN, HN, w1p, G4, KP1,
                                  b_ih1, b_hh1, lens, xg);
    }
    lstm_scan<1><<<BN / 2, 400>>>(xg, nullptr, lens, order, w_hh1, h, nullptr);

    // 4) layer 2 xg GEMM, then scan (hlast only)
    {
        dim3 grid((G4 + 63) / 64, M / 128);
        gemm_tn<1><<<grid, blk>>>(h, M, HN, HN, w2p, G4, KP1,
                                  b_ih2, b_hh2, lens, xg);
    }
    lstm_scan<2><<<BN / 2, 400>>>(xg, nullptr, lens, order, w_hh2, nullptr, hlast);

    // 5) head
    head_kernel<<<1, 256>>>(hlast, w_fc, b_fc, out);
}

// round 5
// speedup vs baseline: 1.7868x; 1.7868x over previous
#include <cuda_runtime.h>
#include <cstddef>
#include <cstdint>

#define VOCABN 50000
#define DIMN   300
#define HN     100
#define TN     512
#define BN     256
#define OUTN   3
#define G4     400   // 4*H
#define G4P    448   // padded N (7 tiles of 64)
#define KP0    304   // padded K for layer-0 table GEMM (emb K=300)
#define KP1    112   // padded K for xg GEMMs (h K=100)

// ---------------- scratch (static device globals; no allocation) ----------------
__device__ float g_table[(size_t)VOCABN * G4];
__device__ float g_xg[(size_t)BN * TN * G4];
__device__ float g_h[(size_t)BN * TN * HN];
__device__ float g_hlast[BN * HN];
__device__ int   g_order[BN];
__device__ float g_w0p[(size_t)G4P * KP0];   // w_ih0 zero-padded to [448,304]
__device__ float g_w1p[(size_t)G4P * KP1];   // w_ih1 zero-padded to [448,112]
__device__ float g_w2p[(size_t)G4P * KP1];   // w_ih2 zero-padded to [448,112]

// ---------------- packed f32x2 helpers (for the scan) ----------------
typedef unsigned long long ull;

__device__ __forceinline__ ull pack2(float x, float y) {
    ull r;
    asm("mov.b64 %0, {%1, %2};" : "=l"(r) : "f"(x), "f"(y));
    return r;
}
__device__ __forceinline__ void unpack2(ull v, float& x, float& y) {
    asm("mov.b64 {%0, %1}, %2;" : "=f"(x), "=f"(y) : "l"(v));
}
__device__ __forceinline__ ull fma2(ull a, ull b, ull c) {
    ull d;
    asm("fma.rn.f32x2 %0, %1, %2, %3;" : "=l"(d) : "l"(a), "l"(b), "l"(c));
    return d;
}

// ---------------- tf32 helpers ----------------
__device__ __forceinline__ uint32_t f2tf(float x) {
    uint32_t r;
    asm("cvt.rna.tf32.f32 %0, %1;" : "=r"(r) : "f"(x));
    return r;
}
__device__ __forceinline__ void cvt_hl(float v, uint32_t& h, uint32_t& l) {
    h = f2tf(v);
    float lo = v - __uint_as_float(h);
    l = f2tf(lo);
}
__device__ __forceinline__ void mma_tf32(float (&d)[4], const uint32_t (&a)[4], const uint32_t (&b)[2]) {
    asm volatile(
        "mma.sync.aligned.m16n8k8.row.col.f32.tf32.tf32.f32 "
        "{%0,%1,%2,%3}, {%4,%5,%6,%7}, {%8,%9}, {%0,%1,%2,%3};"
        : "+f"(d[0]), "+f"(d[1]), "+f"(d[2]), "+f"(d[3])
        : "r"(a[0]), "r"(a[1]), "r"(a[2]), "r"(a[3]), "r"(b[0]), "r"(b[1]));
}

// ---------------- length-descending schedule ----------------
__global__ void sort_order(const int* __restrict__ lengths, int* __restrict__ order)
{
    __shared__ int ls[BN];
    int b = threadIdx.x;
    ls[b] = lengths[b];
    __syncthreads();
    int len = ls[b];
    int rank = 0;
#pragma unroll 8
    for (int j = 0; j < BN; j++) {
        int lj = ls[j];
        rank += (lj > len) || (lj == len && j < b);
    }
    order[rank] = b;
}

// ---------------- weight zero-padding: [400,K] -> [448,Kp] ----------------
__global__ void pad_w(const float* __restrict__ src, float* __restrict__ dst,
                      int K, int Kp)
{
    int idx = blockIdx.x * 256 + threadIdx.x;
    int total = G4P * Kp;
    if (idx >= total) return;
    int r = idx / Kp, k = idx % Kp;
    dst[idx] = (r < G4 && k < K) ? src[r * K + k] : 0.f;
}

// ---------------- 3xTF32 tensor-core GEMM ----------------
// C[m,n] = sum_k A[m,k]*Bp[n,k] + bias1[n] + bias2[n],  N fixed = 400.
// CTA tile 128x64, BK=16, 256 threads = 8 warps (4m x 2n), warp tile 32x32.
// Bp is zero-padded [448, Kp]; A bounds handled by clamping (x zero-padded B).
// SKIP=1: skip tile if its first timestep >= lengths[b] (tiles of 128 rows).
template<int SKIP>
__global__ void __launch_bounds__(256)
gemm_tf32(const float* __restrict__ A, int M, int Ks, int Kreal,
          const float* __restrict__ Bp, int Kp,
          const float* __restrict__ bias1, const float* __restrict__ bias2,
          const int* __restrict__ lengths, float* __restrict__ C)
{
    const int N = G4;
    const int m0 = blockIdx.y * 128;
    const int n0 = blockIdx.x * 64;
    if (SKIP) {
        int b  = m0 / TN;
        int t0 = m0 % TN;           // 512 % 128 == 0
        if (t0 >= lengths[b]) return;
    }

    // smem: m-major, pitch 20 words (gid*20+tq mod 32 -> 32 distinct banks)
    __shared__ uint32_t As_hi[128 * 20], As_lo[128 * 20];
    __shared__ uint32_t Bs_hi[64 * 20],  Bs_lo[64 * 20];
    __shared__ float bias_s[64];

    const int tid  = threadIdx.x;
    const int wid  = tid >> 5;
    const int lane = tid & 31;
    const int wm   = wid & 3;       // warp m index (0..3)
    const int wn   = wid >> 2;      // warp n index (0..1)
    const int gid  = lane >> 2;     // 0..7
    const int tq   = lane & 3;      // 0..3

    if (tid < 64) {
        int n = n0 + tid;
        bias_s[tid] = (n < N) ? bias1[n] + bias2[n] : 0.f;
    }

    // staging coords (constant): A 2 float4/thread, B 1 float4/thread
    int mA[2], kqA[2];
#pragma unroll
    for (int i = 0; i < 2; i++) { int f = i * 256 + tid; mA[i] = f >> 2; kqA[i] = (f & 3) * 4; }
    const int nB = tid >> 2, kqB = (tid & 3) * 4;

    const float* aP[2];
#pragma unroll
    for (int i = 0; i < 2; i++) {
        int mg = m0 + mA[i]; if (mg > M - 1) mg = M - 1;
        aP[i] = A + (size_t)mg * Ks;
    }
    const float* bP = Bp + (size_t)(n0 + nB) * Kp;

    float acc[2][4][4];
#pragma unroll
    for (int i = 0; i < 2; i++)
#pragma unroll
        for (int j = 0; j < 4; j++)
#pragma unroll
            for (int q = 0; q < 4; q++) acc[i][j][q] = 0.f;

    const int kcl = Kreal - 4;
    float4 ra[2], rb;
    // prefetch tile 0
#pragma unroll
    for (int i = 0; i < 2; i++) {
        int kk = kqA[i]; if (kk > kcl) kk = kcl;
        ra[i] = *reinterpret_cast<const float4*>(aP[i] + kk);
    }
    rb = *reinterpret_cast<const float4*>(bP + kqB);

    for (int k0 = 0; k0 < Kp; k0 += 16) {
        // ---- stage regs -> smem (cvt to tf32 hi/lo) ----
#pragma unroll
        for (int i = 0; i < 2; i++) {
            uint32_t h0, l0, h1, l1, h2, l2, h3, l3;
            cvt_hl(ra[i].x, h0, l0); cvt_hl(ra[i].y, h1, l1);
            cvt_hl(ra[i].z, h2, l2); cvt_hl(ra[i].w, h3, l3);
            int off = mA[i] * 20 + kqA[i];
            *reinterpret_cast<uint4*>(&As_hi[off]) = make_uint4(h0, h1, h2, h3);
            *reinterpret_cast<uint4*>(&As_lo[off]) = make_uint4(l0, l1, l2, l3);
        }
        {
            uint32_t h0, l0, h1, l1, h2, l2, h3, l3;
            cvt_hl(rb.x, h0, l0); cvt_hl(rb.y, h1, l1);
            cvt_hl(rb.z, h2, l2); cvt_hl(rb.w, h3, l3);
            int off = nB * 20 + kqB;
            *reinterpret_cast<uint4*>(&Bs_hi[off]) = make_uint4(h0, h1, h2, h3);
            *reinterpret_cast<uint4*>(&Bs_lo[off]) = make_uint4(l0, l1, l2, l3);
        }
        __syncthreads();

        // ---- prefetch next tile (overlaps mma) ----
        int k0n = k0 + 16;
        if (k0n < Kp) {
#pragma unroll
            for (int i = 0; i < 2; i++) {
                int kk = k0n + kqA[i]; if (kk > kcl) kk = kcl;
                ra[i] = *reinterpret_cast<const float4*>(aP[i] + kk);
            }
            rb = *reinterpret_cast<const float4*>(bP + k0n + kqB);
        }

        // ---- mma over 2 k-steps of 8 ----
#pragma unroll
        for (int ks = 0; ks < 2; ks++) {
            const int kb = ks * 8;
            uint32_t ah[2][4], al[2][4];
#pragma unroll
            for (int mf = 0; mf < 2; mf++) {
                int base = (wm * 32 + mf * 16 + gid) * 20 + kb + tq;
                ah[mf][0] = As_hi[base];            al[mf][0] = As_lo[base];
                ah[mf][1] = As_hi[base + 8 * 20];   al[mf][1] = As_lo[base + 8 * 20];
                ah[mf][2] = As_hi[base + 4];        al[mf][2] = As_lo[base + 4];
                ah[mf][3] = As_hi[base + 8 * 20 + 4]; al[mf][3] = As_lo[base + 8 * 20 + 4];
            }
            uint32_t bh[4][2], bl[4][2];
#pragma unroll
            for (int nf = 0; nf < 4; nf++) {
                int base = (wn * 32 + nf * 8 + gid) * 20 + kb + tq;
                bh[nf][0] = Bs_hi[base];     bl[nf][0] = Bs_lo[base];
                bh[nf][1] = Bs_hi[base + 4]; bl[nf][1] = Bs_lo[base + 4];
            }
#pragma unroll
            for (int mf = 0; mf < 2; mf++)
#pragma unroll
                for (int nf = 0; nf < 4; nf++) {
                    mma_tf32(acc[mf][nf], ah[mf], bh[nf]);
                    mma_tf32(acc[mf][nf], ah[mf], bl[nf]);
                    mma_tf32(acc[mf][nf], al[mf], bh[nf]);
                }
        }
        __syncthreads();
    }

    // ---- epilogue ----
#pragma unroll
    for (int mf = 0; mf < 2; mf++) {
#pragma unroll
        for (int nf = 0; nf < 4; nf++) {
            int row0 = m0 + wm * 32 + mf * 16 + gid;
            int cb   = wn * 32 + nf * 8 + 2 * tq;
            int col  = n0 + cb;
            if (col < N) {
                float b0v = bias_s[cb], b1v = bias_s[cb + 1];
                if (row0 < M) {
                    float2 v = make_float2(acc[mf][nf][0] + b0v, acc[mf][nf][1] + b1v);
                    *reinterpret_cast<float2*>(&C[(size_t)row0 * N + col]) = v;
                }
                int row1 = row0 + 8;
                if (row1 < M) {
                    float2 v = make_float2(acc[mf][nf][2] + b0v, acc[mf][nf][3] + b1v);
                    *reinterpret_cast<float2*>(&C[(size_t)row1 * N + col]) = v;
                }
            }
        }
    }
}

// ---------------- LSTM scan (round-3 version: quad-per-hidden-unit) ----------------
__device__ __forceinline__ float tanh_(float x) { return 2.f / (1.f + __expf(-2.f * x)) - 1.f; }

// thread tid = j*4 + g : hidden unit j (0..99), gate g (0=i,1=f,2=g,3=o)
template<int MODE>
__global__ void __launch_bounds__(400, 1)
lstm_scan(const float* __restrict__ xg,
          const int* __restrict__ xtok,
          const int* __restrict__ lengths,
          const int* __restrict__ order,
          const float* __restrict__ w_hh,     // [400,100]
          float* __restrict__ h_out,          // [B,T,100]
          float* __restrict__ hlast)          // [B,100]
{
    const int b   = order[blockIdx.x];
    const int tid = threadIdx.x;
    const int j   = tid >> 2;
    const int g   = tid & 3;
    const int r   = g * 100 + j;

    __shared__ __align__(16) float h_s[2][104];
    __shared__ int idx_s[TN];

    const int len = lengths[b];

    if (MODE == 0) {
        for (int t = tid; t < TN; t += 400) idx_s[t] = xtok[b * TN + t];
    }

    ull w2[50];
    {
        const ull* wrow = reinterpret_cast<const ull*>(w_hh + r * 100);
#pragma unroll
        for (int q = 0; q < 50; q++) w2[q] = wrow[q];
    }

    if (tid < 100) h_s[0][tid] = 0.f;
    float c = 0.f;
    __syncthreads();

    const bool is_t = (g == 2);
    const bool gsel = (g & 2) != 0;

    float xg_next;
    if (MODE == 0) xg_next = xg[(size_t)idx_s[0] * G4 + r];
    else           xg_next = xg[((size_t)b * TN) * G4 + r];

    for (int t = 0; t < len; t++) {
        float xv = xg_next;
        if (t + 1 < len) {
            if (MODE == 0) xg_next = xg[(size_t)idx_s[t + 1] * G4 + r];
            else           xg_next = xg[((size_t)b * TN + t + 1) * G4 + r];
        }
        const ulonglong2* h2 = reinterpret_cast<const ulonglong2*>(h_s[t & 1]);

        ull acc0 = pack2(xv, 0.f);
        ull acc1 = 0ULL;
#pragma unroll
        for (int q = 0; q < 25; q++) {
            ulonglong2 hh = h2[q];
            acc0 = fma2(hh.x, w2[2 * q],     acc0);
            acc1 = fma2(hh.y, w2[2 * q + 1], acc1);
        }
        float a0, a1, a2, a3;
        unpack2(acc0, a0, a1);
        unpack2(acc1, a2, a3);
        float acc = (a0 + a1) + (a2 + a3);

        float z = is_t ? 2.f * acc : acc;
        float s = 1.f / (1.f + __expf(-z));
        float gate = is_t ? (2.f * s - 1.f) : s;

        float v1 = __shfl_xor_sync(0xFFFFFFFFu, gate, 1);
        float pa = (g & 1) ? v1 : gate;
        float pb = (g & 1) ? gate : v1;
        float qa = __shfl_xor_sync(0xFFFFFFFFu, pa, 2);
        float qb = __shfl_xor_sync(0xFFFFFFFFu, pb, 2);
        float ig = gsel ? qa : pa;
        float gg = gsel ? pa : qa;
        float fg = gsel ? qb : pb;
        float og = gsel ? pb : qb;

        c = fg * c + ig * gg;
        float hn = og * tanh_(c);
        if (g == 0) {
            h_s[(t + 1) & 1][j] = hn;
            if (MODE != 2) h_out[((size_t)b * TN + t) * HN + j] = hn;
        }
        if (MODE == 2 && g == 0 && t == len - 1) hlast[b * HN + j] = hn;
        __syncthreads();
    }
}

// ---------------- head ----------------
__global__ void head_kernel(const float* __restrict__ hlast,
                            const float* __restrict__ w_fc,
                            const float* __restrict__ b_fc,
                            float* __restrict__ out)
{
    int b = blockIdx.x * blockDim.x + threadIdx.x;
    if (b >= BN) return;
#pragma unroll
    for (int o = 0; o < OUTN; o++) {
        float s = b_fc[o];
#pragma unroll
        for (int k = 0; k < HN; k++)
            s += hlast[b * HN + k] * w_fc[o * HN + k];
        out[b * OUTN + o] = s;
    }
}

// ---------------- launch ----------------
extern "C" void kernel_launch(void* const* d_in, const int* in_sizes, int n_in,
                              void* d_out, int out_size)
{
    const int*   x      = (const int*)d_in[0];
    const int*   lens   = (const int*)d_in[1];
    const float* emb    = (const float*)d_in[2];
    const float* w_ih0  = (const float*)d_in[3];
    const float* w_hh0  = (const float*)d_in[4];
    const float* b_ih0  = (const float*)d_in[5];
    const float* b_hh0  = (const float*)d_in[6];
    const float* w_ih1  = (const float*)d_in[7];
    const float* w_hh1  = (const float*)d_in[8];
    const float* b_ih1  = (const float*)d_in[9];
    const float* b_hh1  = (const float*)d_in[10];
    const float* w_ih2  = (const float*)d_in[11];
    const float* w_hh2  = (const float*)d_in[12];
    const float* b_ih2  = (const float*)d_in[13];
    const float* b_hh2  = (const float*)d_in[14];
    const float* w_fc   = (const float*)d_in[15];
    const float* b_fc   = (const float*)d_in[16];
    float* out = (float*)d_out;

    void *p_table, *p_xg, *p_h, *p_hlast, *p_order, *p_w0, *p_w1, *p_w2;
    cudaGetSymbolAddress(&p_table, g_table);
    cudaGetSymbolAddress(&p_xg,    g_xg);
    cudaGetSymbolAddress(&p_h,     g_h);
    cudaGetSymbolAddress(&p_hlast, g_hlast);
    cudaGetSymbolAddress(&p_order, g_order);
    cudaGetSymbolAddress(&p_w0,    g_w0p);
    cudaGetSymbolAddress(&p_w1,    g_w1p);
    cudaGetSymbolAddress(&p_w2,    g_w2p);
    float* table = (float*)p_table;
    float* xg    = (float*)p_xg;
    float* h     = (float*)p_h;
    float* hlast = (float*)p_hlast;
    int*   order = (int*)p_order;
    float* w0p   = (float*)p_w0;
    float* w1p   = (float*)p_w1;
    float* w2p   = (float*)p_w2;

    const int M = BN * TN;

    // 0) schedule + weight padding
    sort_order<<<1, BN>>>(lens, order);
    pad_w<<<(G4P * KP0 + 255) / 256, 256>>>(w_ih0, w0p, DIMN, KP0);
    pad_w<<<(G4P * KP1 + 255) / 256, 256>>>(w_ih1, w1p, HN, KP1);
    pad_w<<<(G4P * KP1 + 255) / 256, 256>>>(w_ih2, w2p, HN, KP1);

    // 1) vocab table GEMM: table = emb @ w_ih0^T + b_ih0 + b_hh0
    {
        dim3 grid(7, (VOCABN + 127) / 128);
        gemm_tf32<0><<<grid, 256>>>(emb, VOCABN, DIMN, DIMN, w0p, KP0,
                                    b_ih0, b_hh0, nullptr, table);
    }
    // 2) layer 0 scan (gathers table rows directly)
    lstm_scan<0><<<BN, 400>>>(table, x, lens, order, w_hh0, h, nullptr);

    // 3) layer 1 xg GEMM (+length tile-skip), then scan
    {
        dim3 grid(7, M / 128);
        gemm_tf32<1><<<grid, 256>>>(h, M, HN, HN, w1p, KP1,
                                    b_ih1, b_hh1, lens, xg);
    }
    lstm_scan<1><<<BN, 400>>>(xg, nullptr, lens, order, w_hh1, h, nullptr);

    // 4) layer 2 xg GEMM, then scan (hlast only)
    {
        dim3 grid(7, M / 128);
        gemm_tf32<1><<<grid, 256>>>(h, M, HN, HN, w2p, KP1,
                                    b_ih2, b_hh2, lens, xg);
    }
    lstm_scan<2><<<BN, 400>>>(xg, nullptr, lens, order, w_hh2, nullptr, hlast);

    // 5) head
    head_kernel<<<1, 256>>>(hlast, w_fc, b_fc, out);
}